// round 6
// baseline (speedup 1.0000x reference)
#include <cuda_runtime.h>
#include <cuda_bf16.h>
#include <cstdint>
#include <math.h>

#define B_ROWS 32768
#define R_N 4
#define U_N 256
#define D_N 256
#define NX 768  /* 3*U */
#define NZ 5
#define MT_N 256   /* M tiles: 32768/128 */
#define NT_N 6     /* N tiles: 768/128 */
#define KC_N 4     /* K chunks: 256/64 */
#define MG 32      /* mt groups */
#define MT_PER_CTA 8

#if defined(__CUDA_ARCH__) && (defined(__CUDA_ARCH_FEAT_SM103_ALL) || \
    defined(__CUDA_ARCH_FEAT_SM100_ALL) || defined(__CUDA_ARCH_SPECIFIC__))
#define HAS_TCGEN05 1
#else
#define HAS_TCGEN05 0
#endif

// ---------------- global scratch ----------------
__device__ float g_mx[(size_t)B_ROWS * NX];              // matrix_x  (B, 768)
__device__ float g_inner[(size_t)B_ROWS * R_N * NX];     // matrix_inner (B, 4, 768)

// Pre-swizzled bf16 W tiles, [z][nt][kc], tile = 128 rows x 128B SW128 = 1024 uint4
__device__ uint4 gW_hi[(size_t)NZ * NT_N * KC_N * 1024];
__device__ uint4 gW_lo[(size_t)NZ * NT_N * KC_N * 1024];

// ---------------- PTX helpers ----------------
static __device__ __forceinline__ uint32_t smem_u32(const void* p) {
    uint32_t a;
    asm("{ .reg .u64 t; cvta.to.shared.u64 t, %1; cvt.u32.u64 %0, t; }" : "=r"(a) : "l"(p));
    return a;
}
static __device__ __forceinline__ uint32_t elect1() {
    uint32_t p;
    asm volatile("{\n\t.reg .pred p;\n\telect.sync _|p, 0xFFFFFFFF;\n\tselp.b32 %0, 1, 0, p;\n\t}" : "=r"(p));
    return p;
}
#define SMEM_DESC_BASE ((2ull<<61)|(1ull<<46)|(64ull<<32)|(1ull<<16))
static __device__ __forceinline__ uint64_t make_desc(uint32_t addr) {
    return SMEM_DESC_BASE | ((uint64_t)(addr >> 4) & 0x3FFFull);
}
#define IDESC_BF16 ((1u<<4)|(1u<<7)|(1u<<10)|((128u/8u)<<17)|((128u/16u)<<24))

#define MBAR_INIT(addr, cnt) \
    asm volatile("mbarrier.init.shared.b64 [%0], %1;" :: "r"(addr), "r"(cnt) : "memory")
#define MBAR_INVAL(addr) \
    asm volatile("mbarrier.inval.shared.b64 [%0];" :: "r"(addr) : "memory")
#define MBAR_WAIT(addr, parity) do {                                              \
    uint32_t _m = (addr), _p = (parity), _d;                                      \
    asm volatile("{\n\t.reg .pred p;\n\t"                                         \
        "mbarrier.try_wait.parity.acquire.cta.shared::cta.b64 p, [%1], %2;\n\t"   \
        "selp.b32 %0, 1, 0, p;\n\t}" : "=r"(_d) : "r"(_m), "r"(_p) : "memory");   \
    if (!_d) {                                                                    \
        asm volatile("{\n\t.reg .pred P1;\n\t"                                    \
            "WL_%=:\n\t"                                                          \
            "mbarrier.try_wait.parity.acquire.cta.shared::cta.b64 P1, [%0], %1, 0x989680;\n\t" \
            "@P1 bra.uni WD_%=;\n\t"                                              \
            "bra.uni WL_%=;\n\t"                                                  \
            "WD_%=:\n\t}" :: "r"(_m), "r"(_p) : "memory");                        \
    } } while (0)

#if HAS_TCGEN05
static __device__ __forceinline__ void mma_f16_ss(uint32_t d_tmem, uint64_t a_desc,
                                                  uint64_t b_desc, uint32_t en) {
    asm volatile(
        "{\n\t"
        ".reg .pred p;\n\t"
        "setp.ne.u32 p, %4, 0;\n\t"
        "tcgen05.mma.cta_group::1.kind::f16 [%0], %1, %2, %3, {%5, %5, %5, %5}, p;\n\t"
        "}"
        :: "r"(d_tmem), "l"(a_desc), "l"(b_desc), "r"(IDESC_BF16), "r"(en), "r"(0u)
        : "memory");
}
#define TC_LD_X32(r, addr)                                                        \
    asm volatile("tcgen05.ld.sync.aligned.32x32b.x32.b32 "                        \
        "{%0, %1, %2, %3, %4, %5, %6, %7, "                                       \
        " %8, %9, %10, %11, %12, %13, %14, %15, "                                 \
        " %16, %17, %18, %19, %20, %21, %22, %23, "                               \
        " %24, %25, %26, %27, %28, %29, %30, %31}, [%32];"                        \
        : "=r"((r)[0]),  "=r"((r)[1]),  "=r"((r)[2]),  "=r"((r)[3]),              \
          "=r"((r)[4]),  "=r"((r)[5]),  "=r"((r)[6]),  "=r"((r)[7]),              \
          "=r"((r)[8]),  "=r"((r)[9]),  "=r"((r)[10]), "=r"((r)[11]),             \
          "=r"((r)[12]), "=r"((r)[13]), "=r"((r)[14]), "=r"((r)[15]),             \
          "=r"((r)[16]), "=r"((r)[17]), "=r"((r)[18]), "=r"((r)[19]),             \
          "=r"((r)[20]), "=r"((r)[21]), "=r"((r)[22]), "=r"((r)[23]),             \
          "=r"((r)[24]), "=r"((r)[25]), "=r"((r)[26]), "=r"((r)[27]),             \
          "=r"((r)[28]), "=r"((r)[29]), "=r"((r)[30]), "=r"((r)[31])              \
        : "r"(addr))
#endif

// ---------------- prep_W: fp32 -> bf16 hi/lo pre-swizzled W tiles ----------------
__global__ void __launch_bounds__(256) prep_W(const float* __restrict__ kernelW,
                                              const float* __restrict__ rkernel) {
    unsigned i = blockIdx.x * 256u + threadIdx.x;      // < 122880
    unsigned g   = i & 7u;
    unsigned nr  = (i >> 3) & 127u;
    unsigned top = i >> 10;           // (z*6+nt)*4+kc
    unsigned kc  = top & 3u;
    unsigned tz  = top >> 2;
    unsigned z   = tz / 6u;
    unsigned nt  = tz % 6u;
    unsigned ncol = nt * 128u + nr;
    unsigned hs[8], ls[8];
#pragma unroll
    for (int j = 0; j < 8; j++) {
        unsigned k = kc * 64u + g * 8u + j;
        float x = (z == 0) ? kernelW[(size_t)k * NX + ncol]
                           : rkernel[((size_t)(z - 1) * U_N + k) * NX + ncol];
        __nv_bfloat16 h = __float2bfloat16_rn(x);
        hs[j] = (unsigned)__bfloat16_as_ushort(h);
        float hf = __bfloat162float(h);
        ls[j] = (unsigned)__bfloat16_as_ushort(__float2bfloat16_rn(x - hf));
    }
    uint4 uh, ul;
    uh.x = hs[0] | (hs[1] << 16); uh.y = hs[2] | (hs[3] << 16);
    uh.z = hs[4] | (hs[5] << 16); uh.w = hs[6] | (hs[7] << 16);
    ul.x = ls[0] | (ls[1] << 16); ul.y = ls[2] | (ls[3] << 16);
    ul.z = ls[4] | (ls[5] << 16); ul.w = ls[6] | (ls[7] << 16);
    unsigned byte = (i & 1023u) * 16u;
    unsigned sw = byte ^ ((byte >> 3) & 0x70u);
    gW_hi[(size_t)top * 1024 + (sw >> 4)] = uh;
    gW_lo[(size_t)top * 1024 + (sw >> 4)] = ul;
}

static __device__ __forceinline__ float rd_bf16_sw(const char* base, int row, int col) {
    unsigned byte = (unsigned)row * 128u + (unsigned)col * 2u;
    unsigned sw = byte ^ ((byte >> 3) & 0x70u);
    unsigned short u = *(const unsigned short*)(base + sw);
    return __bfloat162float(__ushort_as_bfloat16(u));
}

// ---------------- persistent-W pipelined tcgen05 GEMM ----------------
// SMEM layout from tb (1024-aligned): W 128KB | A 2x32KB | stage 32KB
#define SM_W 0
#define SM_A 131072
#define SM_STAGE 196608
#define DSMEM_BYTES 231424

__global__ void __launch_bounds__(256) gemm_tc(
    const float* __restrict__ inputs,
    const float* __restrict__ states,
    const float* __restrict__ bias)
{
    extern __shared__ __align__(16) char smem[];
    const uint32_t sb = smem_u32(smem);
    const int tid = threadIdx.x, wid = tid >> 5, lane = tid & 31;
    const int nt = blockIdx.x, z = blockIdx.y, mtg = blockIdx.z;

    const uint32_t tb = (sb + 1024u + 1023u) & ~1023u;
    char* tbp = smem + (tb - sb);
    const uint32_t ml0 = sb + 8;   // load barrier, A buffer 0
    const uint32_t ml1 = sb + 16;  // load barrier, A buffer 1
    const uint32_t me  = sb + 24;  // epilogue barrier

    // ---- load W tile-set once: [kc][hi/lo] 8 x 1024 uint4 ----
    {
        uint4* sW = (uint4*)(tbp + SM_W);
        const size_t wbase = (size_t)((z * NT_N + nt) * KC_N) * 1024;
#pragma unroll
        for (int it = 0; it < 32; it++) {
            int idx = tid + it * 256;             // 0..8191
            int kc = idx >> 11, h = (idx >> 10) & 1, j = idx & 1023;
            sW[(kc * 2 + h) * 1024 + j] = h ? gW_lo[wbase + kc * 1024 + j]
                                            : gW_hi[wbase + kc * 1024 + j];
        }
    }

#if HAS_TCGEN05
    if (wid == 0) {
        asm volatile("tcgen05.alloc.cta_group::1.sync.aligned.shared::cta.b32 [%0], %1;"
                     :: "r"(sb), "r"(256u) : "memory");
        asm volatile("tcgen05.relinquish_alloc_permit.cta_group::1.sync.aligned;");
    }
    if (tid == 0) { MBAR_INIT(ml0, 1u); MBAR_INIT(ml1, 1u); MBAR_INIT(me, 1u); }
    asm volatile("fence.proxy.async.shared::cta;" ::: "memory");
    __syncthreads();
    uint32_t tmem;
    asm volatile("ld.shared.b32 %0, [%1];" : "=r"(tmem) : "r"(sb));

    const int lda = (z == 0) ? D_N : (R_N * U_N);
    const float* Abase = (z == 0) ? inputs : (states + (z - 1) * U_N);

    // thread's fixed A-load coords
    const unsigned g8 = (unsigned)(tid & 7);          // 16B group within row
    const unsigned arw = (unsigned)(tid >> 3);        // row base (32 rows per j-pass)

    // epilogue constants
    const int ewc = (wid >> 2);                       // 0/1: col-quarter within 64-chunk
    const int esub = (wid & 3);                       // subpartition/rows
    const float* brow = bias + (size_t)z * NX + nt * 128;

    for (int s = 0; s < MT_PER_CTA * KC_N; s++) {
        const int m = s >> 2, kc = s & 3, buf = s & 1;
        const int jj = s >> 1;
        const int mt = mtg * MT_PER_CTA + m;
        const uint32_t mlb = buf ? ml1 : ml0;
        // Per-buffer barrier: the j-th commit on buffer b happens at step 2j+b.
        // Wait at step s=2j+b for commit j-1 -> parity (j-1)&1. Exact (no alias):
        // commits landed on this barrier <= j because commit j is issued later.
        if (s >= 2) MBAR_WAIT(mlb, (unsigned)((jj - 1) & 1));
        // ---- load + convert A chunk: 128 rows x 64 k ----
        {
            uint4* sAh = (uint4*)(tbp + SM_A + buf * 32768);
            uint4* sAl = (uint4*)(tbp + SM_A + buf * 32768 + 16384);
            const float* srcb = Abase + (size_t)(mt * 128) * lda + kc * 64 + g8 * 8;
#pragma unroll
            for (int j = 0; j < 4; j++) {
                unsigned row = arw + j * 32;
                const float* src = srcb + (size_t)row * lda;
                float4 f0 = *(const float4*)src;
                float4 f1 = *(const float4*)(src + 4);
                float x[8] = {f0.x, f0.y, f0.z, f0.w, f1.x, f1.y, f1.z, f1.w};
                unsigned hs[8], lsv[8];
#pragma unroll
                for (int e = 0; e < 8; e++) {
                    __nv_bfloat16 h = __float2bfloat16_rn(x[e]);
                    hs[e] = (unsigned)__bfloat16_as_ushort(h);
                    lsv[e] = (unsigned)__bfloat16_as_ushort(
                        __float2bfloat16_rn(x[e] - __bfloat162float(h)));
                }
                uint4 uh, ul;
                uh.x = hs[0] | (hs[1] << 16); uh.y = hs[2] | (hs[3] << 16);
                uh.z = hs[4] | (hs[5] << 16); uh.w = hs[6] | (hs[7] << 16);
                ul.x = lsv[0] | (lsv[1] << 16); ul.y = lsv[2] | (lsv[3] << 16);
                ul.z = lsv[4] | (lsv[5] << 16); ul.w = lsv[6] | (lsv[7] << 16);
                unsigned byte = row * 128u + g8 * 16u;
                unsigned sw = byte ^ ((byte >> 3) & 0x70u);
                sAh[sw >> 4] = uh;
                sAl[sw >> 4] = ul;
            }
        }
        asm volatile("fence.proxy.async.shared::cta;" ::: "memory");
        __syncthreads();
        // ---- MMAs for this step ----
        if (wid == 0 && elect1()) {
            const uint32_t dcol = ((unsigned)(m & 1)) * 128u;
            const uint64_t dAh = make_desc(tb + SM_A + buf * 32768);
            const uint64_t dAl = make_desc(tb + SM_A + buf * 32768 + 16384);
            const uint64_t dBh = make_desc(tb + SM_W + (kc * 2 + 0) * 16384);
            const uint64_t dBl = make_desc(tb + SM_W + (kc * 2 + 1) * 16384);
#pragma unroll
            for (int ks = 0; ks < 4; ks++) {
                uint64_t off = (uint64_t)(ks * 2);
                mma_f16_ss(tmem + dcol, dAh + off, dBh + off, (kc == 0 && ks == 0) ? 0u : 1u);
                mma_f16_ss(tmem + dcol, dAh + off, dBl + off, 1u);
                mma_f16_ss(tmem + dcol, dAl + off, dBh + off, 1u);
            }
            asm volatile(
                "tcgen05.commit.cta_group::1.mbarrier::arrive::one.shared::cluster.b64 [%0];"
                :: "r"(mlb) : "memory");
            if (kc == 3)
                asm volatile(
                    "tcgen05.commit.cta_group::1.mbarrier::arrive::one.shared::cluster.b64 [%0];"
                    :: "r"(me) : "memory");
        }
        // ---- overlapped epilogue for previous mt ----
        if (kc == 0 && m >= 1) {
            const int pm = m - 1;
            const int pmt = mtg * MT_PER_CTA + pm;
            MBAR_WAIT(me, (unsigned)(pm & 1));
            asm volatile("tcgen05.fence::after_thread_sync;" ::: "memory");
            const uint32_t dcol = ((unsigned)(pm & 1)) * 128u;
#pragma unroll
            for (int half = 0; half < 2; half++) {
                uint32_t r[32];
                TC_LD_X32(r, tmem + dcol + (uint32_t)(half * 64 + ewc * 32));
                asm volatile("tcgen05.wait::ld.sync.aligned;" ::: "memory");
                const int srow = esub * 32 + lane;
#pragma unroll
                for (int q = 0; q < 8; q++) {
                    const int c = ewc * 32 + q * 4;                  // col in 64-chunk
                    const float4 b4 = *(const float4*)(brow + half * 64 + c);
                    float4 f;
                    f.x = __uint_as_float(r[q*4+0]) + b4.x;
                    f.y = __uint_as_float(r[q*4+1]) + b4.y;
                    f.z = __uint_as_float(r[q*4+2]) + b4.z;
                    f.w = __uint_as_float(r[q*4+3]) + b4.w;
                    const unsigned c16 = (unsigned)(c >> 2);
                    const unsigned phys = (unsigned)srow * 256u + ((c16 ^ ((unsigned)srow & 15u)) << 4);
                    *(float4*)(tbp + SM_STAGE + phys) = f;
                }
                __syncthreads();
#pragma unroll
                for (int it = 0; it < 8; it++) {
                    const int i2 = tid + it * 256;
                    const int rw = i2 >> 4, c16r = i2 & 15;
                    const unsigned phys = (unsigned)rw * 256u + (((unsigned)c16r ^ ((unsigned)rw & 15u)) << 4);
                    const float4 f = *(const float4*)(tbp + SM_STAGE + phys);
                    const size_t rg = (size_t)pmt * 128 + rw;
                    const int ncol = nt * 128 + half * 64 + c16r * 4;
                    float* dst = (z == 0)
                        ? (g_mx + rg * NX + ncol)
                        : (g_inner + rg * (R_N * NX) + (size_t)(z - 1) * NX + ncol);
                    *(float4*)dst = f;
                }
                __syncthreads();
            }
        }
    }
    // ---- drain: epilogue for last mt ----
    {
        const int pm = MT_PER_CTA - 1;
        const int pmt = mtg * MT_PER_CTA + pm;
        MBAR_WAIT(me, (unsigned)(pm & 1));
        asm volatile("tcgen05.fence::after_thread_sync;" ::: "memory");
        const uint32_t dcol = ((unsigned)(pm & 1)) * 128u;
#pragma unroll
        for (int half = 0; half < 2; half++) {
            uint32_t r[32];
            TC_LD_X32(r, tmem + dcol + (uint32_t)(half * 64 + ewc * 32));
            asm volatile("tcgen05.wait::ld.sync.aligned;" ::: "memory");
            const int srow = esub * 32 + lane;
#pragma unroll
            for (int q = 0; q < 8; q++) {
                const int c = ewc * 32 + q * 4;
                const float4 b4 = *(const float4*)(brow + half * 64 + c);
                float4 f;
                f.x = __uint_as_float(r[q*4+0]) + b4.x;
                f.y = __uint_as_float(r[q*4+1]) + b4.y;
                f.z = __uint_as_float(r[q*4+2]) + b4.z;
                f.w = __uint_as_float(r[q*4+3]) + b4.w;
                const unsigned c16 = (unsigned)(c >> 2);
                const unsigned phys = (unsigned)srow * 256u + ((c16 ^ ((unsigned)srow & 15u)) << 4);
                *(float4*)(tbp + SM_STAGE + phys) = f;
            }
            __syncthreads();
#pragma unroll
            for (int it = 0; it < 8; it++) {
                const int i2 = tid + it * 256;
                const int rw = i2 >> 4, c16r = i2 & 15;
                const unsigned phys = (unsigned)rw * 256u + (((unsigned)c16r ^ ((unsigned)rw & 15u)) << 4);
                const float4 f = *(const float4*)(tbp + SM_STAGE + phys);
                const size_t rg = (size_t)pmt * 128 + rw;
                const int ncol = nt * 128 + half * 64 + c16r * 4;
                float* dst = (z == 0)
                    ? (g_mx + rg * NX + ncol)
                    : (g_inner + rg * (R_N * NX) + (size_t)(z - 1) * NX + ncol);
                *(float4*)dst = f;
            }
            __syncthreads();
        }
    }
    if (tid == 0) { MBAR_INVAL(ml0); MBAR_INVAL(ml1); MBAR_INVAL(me); }
    __syncthreads();
    if (wid == 0) {
        asm volatile("tcgen05.dealloc.cta_group::1.sync.aligned.b32 %0, %1;"
                     :: "r"(tmem), "r"(256u));
    }
#else
    // fp32 fallback (never executed when sm_103a cubin present)
    __syncthreads();
    const int lda = (z == 0) ? D_N : (R_N * U_N);
    const float* Abase = (z == 0) ? inputs : (states + (z - 1) * U_N);
    for (int m = 0; m < MT_PER_CTA; m++) {
        const int mt = mtg * MT_PER_CTA + m;
        float facc[64];
#pragma unroll
        for (int j = 0; j < 64; j++) facc[j] = 0.f;
        const int frow = tid >> 1;
        const int fc0 = (tid & 1) * 64;
        for (int kc = 0; kc < KC_N; kc++) {
            for (int kk = 0; kk < 64; kk++) {
                float a = Abase[(size_t)(mt * 128 + frow) * lda + kc * 64 + kk];
                const char* wh = tbp + SM_W + (kc * 2 + 0) * 16384;
                const char* wl = tbp + SM_W + (kc * 2 + 1) * 16384;
#pragma unroll 8
                for (int j = 0; j < 64; j++) {
                    float bb = rd_bf16_sw(wh, fc0 + j, kk) + rd_bf16_sw(wl, fc0 + j, kk);
                    facc[j] = fmaf(a, bb, facc[j]);
                }
            }
        }
        size_t rg = (size_t)mt * 128 + frow;
        const int n0 = nt * 128;
#pragma unroll 8
        for (int j = 0; j < 64; j++) {
            float f = facc[j] + bias[(size_t)z * NX + n0 + fc0 + j];
            float* dst = (z == 0)
                ? (g_mx + rg * NX + n0 + fc0 + j)
                : (g_inner + rg * (R_N * NX) + (size_t)(z - 1) * NX + n0 + fc0 + j);
            *dst = f;
        }
    }
#endif
}

// ---------------- vectorized fused epilogue: 4 rows/block, float4/thread ----------------
static __device__ __forceinline__ float4 ld4(const float* p) { return *(const float4*)p; }

__global__ void __launch_bounds__(256) fuse_kernel(
    const float* __restrict__ states,
    const int* __restrict__ cell_mask,
    const float* __restrict__ v,
    float* __restrict__ out)
{
    const int rin = threadIdx.x >> 6;                 // row in block 0..3
    const int b = blockIdx.x * 4 + rin;
    const int t = threadIdx.x & 63;
    const int u0 = t * 4;

    const float* mxp = g_mx + (size_t)b * NX;
    const float4 xz = ld4(mxp + u0);
    const float4 xr = ld4(mxp + U_N + u0);
    const float4 xh = ld4(mxp + 2 * U_N + u0);

    bool m[R_N];
#pragma unroll
    for (int r = 0; r < R_N; r++) m[r] = cell_mask[b * R_N + r] != 0;

    float4 rz[R_N];
    float4 acc = make_float4(0.f, 0.f, 0.f, 0.f);
#pragma unroll
    for (int r = 0; r < R_N; r++) {
        const float* ip = g_inner + (size_t)b * (R_N * NX) + (size_t)r * NX;
        rz[r] = ld4(ip + u0);
        const float4 rr  = ld4(ip + U_N + u0);
        const float4 rhc = ld4(ip + 2 * U_N + u0);
        if (m[r]) {
            acc.x += rhc.x / (1.0f + expf(-(xr.x + rr.x)));
            acc.y += rhc.y / (1.0f + expf(-(xr.y + rr.y)));
            acc.z += rhc.z / (1.0f + expf(-(xr.z + rr.z)));
            acc.w += rhc.w / (1.0f + expf(-(xr.w + rr.w)));
        }
    }
    float4 hh;
    hh.x = tanhf(xh.x + acc.x * 0.25f);
    hh.y = tanhf(xh.y + acc.y * 0.25f);
    hh.z = tanhf(xh.z + acc.z * 0.25f);
    hh.w = tanhf(xh.w + acc.w * 0.25f);

    const float4 vv = ld4(v + u0);
    float part[R_N + 1];
#pragma unroll
    for (int r = 0; r < R_N; r++) {
        part[r] = tanhf(xz.x + rz[r].x) * vv.x + tanhf(xz.y + rz[r].y) * vv.y
                + tanhf(xz.z + rz[r].z) * vv.z + tanhf(xz.w + rz[r].w) * vv.w;
    }
    part[R_N] = tanhf(xz.x + hh.x) * vv.x + tanhf(xz.y + hh.y) * vv.y
              + tanhf(xz.z + hh.z) * vv.z + tanhf(xz.w + hh.w) * vv.w;

    __shared__ float wsum[8][R_N + 1];
    const int warp = threadIdx.x >> 5;
    const int lane = threadIdx.x & 31;
#pragma unroll
    for (int k = 0; k < R_N + 1; k++) {
        float s = part[k];
#pragma unroll
        for (int off = 16; off > 0; off >>= 1)
            s += __shfl_down_sync(0xffffffffu, s, off);
        if (lane == 0) wsum[warp][k] = s;
    }
    __shared__ float prob_s[4][R_N + 1];
    __syncthreads();
    if (t == 0) {
        float logit[R_N + 1];
        float mx = -INFINITY;
#pragma unroll
        for (int k = 0; k < R_N + 1; k++) {
            float s = wsum[rin * 2][k] + wsum[rin * 2 + 1][k];
            const bool ok = (k == R_N) ? true : m[k];
            logit[k] = ok ? s : -INFINITY;
            mx = fmaxf(mx, logit[k]);
        }
        float denom = 0.f;
        float e[R_N + 1];
#pragma unroll
        for (int k = 0; k < R_N + 1; k++) {
            e[k] = (logit[k] == -INFINITY) ? 0.f : expf(logit[k] - mx);
            denom += e[k];
        }
#pragma unroll
        for (int k = 0; k < R_N + 1; k++) prob_s[rin][k] = e[k] / denom;
    }
    __syncthreads();

    float4 h = make_float4(0.f, 0.f, 0.f, 0.f);
#pragma unroll
    for (int r = 0; r < R_N; r++) {
        const float4 st = ld4(states + (size_t)b * (R_N * U_N) + r * U_N + u0);
        const float p = prob_s[rin][r];
        h.x += st.x * p; h.y += st.y * p; h.z += st.z * p; h.w += st.w * p;
    }
    const float p4 = prob_s[rin][R_N];
    h.x += hh.x * p4; h.y += hh.y * p4; h.z += hh.z * p4; h.w += hh.w * p4;
    *(float4*)(out + (size_t)b * U_N + u0) = h;
}

extern "C" void kernel_launch(void* const* d_in, const int* in_sizes, int n_in,
                              void* d_out, int out_size) {
    const float* inputs    = (const float*)d_in[0];
    const float* states    = (const float*)d_in[1];
    /* d_in[2] = edge_types (dead in reference) */
    const int*   cell_mask = (const int*)d_in[3];
    const float* kernelW   = (const float*)d_in[4];
    const float* rkernel   = (const float*)d_in[5];
    const float* bias      = (const float*)d_in[6];
    const float* v         = (const float*)d_in[7];
    /* d_in[8] = edge_emb (dead in reference) */
    float* out = (float*)d_out;
    (void)in_sizes; (void)n_in; (void)out_size;

    cudaFuncSetAttribute(gemm_tc, cudaFuncAttributeMaxDynamicSharedMemorySize, DSMEM_BYTES);

    prep_W<<<480, 256>>>(kernelW, rkernel);
    gemm_tc<<<dim3(NT_N, NZ, MG), 256, DSMEM_BYTES>>>(inputs, states, bias);
    fuse_kernel<<<B_ROWS / 4, 256>>>(states, cell_mask, v, out);
}

// round 7
// speedup vs baseline: 1.5031x; 1.5031x over previous
#include <cuda_runtime.h>
#include <cuda_bf16.h>
#include <cstdint>
#include <math.h>

#define B_ROWS 32768
#define R_N 4
#define U_N 256
#define D_N 256
#define NX 768  /* 3*U */
#define NZ 5
#define MT_N 256   /* M tiles: 32768/128 */
#define NT_N 6     /* N tiles: 768/128 */
#define KC_N 4     /* K chunks: 256/64 */

#if defined(__CUDA_ARCH__) && (defined(__CUDA_ARCH_FEAT_SM103_ALL) || \
    defined(__CUDA_ARCH_FEAT_SM100_ALL) || defined(__CUDA_ARCH_SPECIFIC__))
#define HAS_TCGEN05 1
#else
#define HAS_TCGEN05 0
#endif

// ---------------- global scratch ----------------
__device__ float g_mx[(size_t)B_ROWS * NX];              // matrix_x  (B, 768)
__device__ float g_inner[(size_t)B_ROWS * R_N * NX];     // matrix_inner (B, 4, 768)

// Pre-swizzled bf16 W tiles, [z][nt][kc], tile = 128 rows x 128B SW128 = 1024 uint4
__device__ uint4 gW_hi[(size_t)NZ * NT_N * KC_N * 1024];
__device__ uint4 gW_lo[(size_t)NZ * NT_N * KC_N * 1024];

// ---------------- PTX helpers ----------------
static __device__ __forceinline__ uint32_t smem_u32(const void* p) {
    uint32_t a;
    asm("{ .reg .u64 t; cvta.to.shared.u64 t, %1; cvt.u32.u64 %0, t; }" : "=r"(a) : "l"(p));
    return a;
}
static __device__ __forceinline__ uint32_t elect1() {
    uint32_t p;
    asm volatile("{\n\t.reg .pred p;\n\telect.sync _|p, 0xFFFFFFFF;\n\tselp.b32 %0, 1, 0, p;\n\t}" : "=r"(p));
    return p;
}
#define SMEM_DESC_BASE ((2ull<<61)|(1ull<<46)|(64ull<<32)|(1ull<<16))
static __device__ __forceinline__ uint64_t make_desc(uint32_t addr) {
    return SMEM_DESC_BASE | ((uint64_t)(addr >> 4) & 0x3FFFull);
}
#define IDESC_BF16 ((1u<<4)|(1u<<7)|(1u<<10)|((128u/8u)<<17)|((128u/16u)<<24))

#define MBAR_INIT(addr, cnt) \
    asm volatile("mbarrier.init.shared.b64 [%0], %1;" :: "r"(addr), "r"(cnt) : "memory")
#define MBAR_INVAL(addr) \
    asm volatile("mbarrier.inval.shared.b64 [%0];" :: "r"(addr) : "memory")
#define MBAR_WAIT(addr, parity) do {                                              \
    uint32_t _m = (addr), _p = (parity), _d;                                      \
    asm volatile("{\n\t.reg .pred p;\n\t"                                         \
        "mbarrier.try_wait.parity.acquire.cta.shared::cta.b64 p, [%1], %2;\n\t"   \
        "selp.b32 %0, 1, 0, p;\n\t}" : "=r"(_d) : "r"(_m), "r"(_p) : "memory");   \
    if (!_d) {                                                                    \
        asm volatile("{\n\t.reg .pred P1;\n\t"                                    \
            "WL_%=:\n\t"                                                          \
            "mbarrier.try_wait.parity.acquire.cta.shared::cta.b64 P1, [%0], %1, 0x989680;\n\t" \
            "@P1 bra.uni WD_%=;\n\t"                                              \
            "bra.uni WL_%=;\n\t"                                                  \
            "WD_%=:\n\t}" :: "r"(_m), "r"(_p) : "memory");                        \
    } } while (0)

#if HAS_TCGEN05
static __device__ __forceinline__ void mma_f16_ss(uint32_t d_tmem, uint64_t a_desc,
                                                  uint64_t b_desc, uint32_t en) {
    asm volatile(
        "{\n\t"
        ".reg .pred p;\n\t"
        "setp.ne.u32 p, %4, 0;\n\t"
        "tcgen05.mma.cta_group::1.kind::f16 [%0], %1, %2, %3, {%5, %5, %5, %5}, p;\n\t"
        "}"
        :: "r"(d_tmem), "l"(a_desc), "l"(b_desc), "r"(IDESC_BF16), "r"(en), "r"(0u)
        : "memory");
}
#define TC_LD_X32(r, addr)                                                        \
    asm volatile("tcgen05.ld.sync.aligned.32x32b.x32.b32 "                        \
        "{%0, %1, %2, %3, %4, %5, %6, %7, "                                       \
        " %8, %9, %10, %11, %12, %13, %14, %15, "                                 \
        " %16, %17, %18, %19, %20, %21, %22, %23, "                               \
        " %24, %25, %26, %27, %28, %29, %30, %31}, [%32];"                        \
        : "=r"((r)[0]),  "=r"((r)[1]),  "=r"((r)[2]),  "=r"((r)[3]),              \
          "=r"((r)[4]),  "=r"((r)[5]),  "=r"((r)[6]),  "=r"((r)[7]),              \
          "=r"((r)[8]),  "=r"((r)[9]),  "=r"((r)[10]), "=r"((r)[11]),             \
          "=r"((r)[12]), "=r"((r)[13]), "=r"((r)[14]), "=r"((r)[15]),             \
          "=r"((r)[16]), "=r"((r)[17]), "=r"((r)[18]), "=r"((r)[19]),             \
          "=r"((r)[20]), "=r"((r)[21]), "=r"((r)[22]), "=r"((r)[23]),             \
          "=r"((r)[24]), "=r"((r)[25]), "=r"((r)[26]), "=r"((r)[27]),             \
          "=r"((r)[28]), "=r"((r)[29]), "=r"((r)[30]), "=r"((r)[31])              \
        : "r"(addr))
#endif

// ---------------- prep_W: fp32 -> bf16 hi/lo pre-swizzled W tiles ----------------
__global__ void __launch_bounds__(256) prep_W(const float* __restrict__ kernelW,
                                              const float* __restrict__ rkernel) {
    unsigned i = blockIdx.x * 256u + threadIdx.x;      // < 122880
    unsigned g   = i & 7u;
    unsigned nr  = (i >> 3) & 127u;
    unsigned top = i >> 10;           // (z*6+nt)*4+kc
    unsigned kc  = top & 3u;
    unsigned tz  = top >> 2;
    unsigned z   = tz / 6u;
    unsigned nt  = tz % 6u;
    unsigned ncol = nt * 128u + nr;
    unsigned hs[8], ls[8];
#pragma unroll
    for (int j = 0; j < 8; j++) {
        unsigned k = kc * 64u + g * 8u + j;
        float x = (z == 0) ? kernelW[(size_t)k * NX + ncol]
                           : rkernel[((size_t)(z - 1) * U_N + k) * NX + ncol];
        __nv_bfloat16 h = __float2bfloat16_rn(x);
        hs[j] = (unsigned)__bfloat16_as_ushort(h);
        float hf = __bfloat162float(h);
        ls[j] = (unsigned)__bfloat16_as_ushort(__float2bfloat16_rn(x - hf));
    }
    uint4 uh, ul;
    uh.x = hs[0] | (hs[1] << 16); uh.y = hs[2] | (hs[3] << 16);
    uh.z = hs[4] | (hs[5] << 16); uh.w = hs[6] | (hs[7] << 16);
    ul.x = ls[0] | (ls[1] << 16); ul.y = ls[2] | (ls[3] << 16);
    ul.z = ls[4] | (ls[5] << 16); ul.w = ls[6] | (ls[7] << 16);
    unsigned byte = (i & 1023u) * 16u;
    unsigned sw = byte ^ ((byte >> 3) & 0x70u);
    gW_hi[(size_t)top * 1024 + (sw >> 4)] = uh;
    gW_lo[(size_t)top * 1024 + (sw >> 4)] = ul;
}

static __device__ __forceinline__ float rd_bf16_sw(const char* base, int row, int col) {
    unsigned byte = (unsigned)row * 128u + (unsigned)col * 2u;
    unsigned sw = byte ^ ((byte >> 3) & 0x70u);
    unsigned short u = *(const unsigned short*)(base + sw);
    return __bfloat162float(__ushort_as_bfloat16(u));
}

// ---------------- tcgen05 GEMM (round-4 structure + in-kernel A conversion) ----------------
// D(128x128 fp32 in TMEM) = A(128x256 fp32->bf16 hi/lo) * W(256x128 bf16 hi/lo)
// 3 bf16 passes per K16-step: Ah*Wh + Ah*Wl + Al*Wh
#define DSMEM_BYTES 67584

__global__ void __launch_bounds__(256) gemm_tc(
    const float* __restrict__ inputs,
    const float* __restrict__ states,
    const float* __restrict__ bias)
{
    extern __shared__ __align__(16) char smem[];
    const uint32_t sb = smem_u32(smem);
    const int tid = threadIdx.x, wid = tid >> 5, lane = tid & 31;
    const int nt = blockIdx.x, mt = blockIdx.y, z = blockIdx.z;

    const uint32_t tb = (sb + 1024u + 1023u) & ~1023u;
    char* tbp = smem + (tb - sb);

#if HAS_TCGEN05
    if (wid == 0) {
        asm volatile("tcgen05.alloc.cta_group::1.sync.aligned.shared::cta.b32 [%0], %1;"
                     :: "r"(sb), "r"(128u) : "memory");
        asm volatile("tcgen05.relinquish_alloc_permit.cta_group::1.sync.aligned;");
    }
    if (tid == 0) MBAR_INIT(sb + 8, 1u);
    __syncthreads();
    uint32_t tmem;
    asm volatile("ld.shared.b32 %0, [%1];" : "=r"(tmem) : "r"(sb));
#else
    float facc[64];
#pragma unroll
    for (int j = 0; j < 64; j++) facc[j] = 0.f;
#endif

    uint4* sAh = (uint4*)(tbp);
    uint4* sAl = (uint4*)(tbp + 16384);
    uint4* sWh = (uint4*)(tbp + 32768);
    uint4* sWl = (uint4*)(tbp + 49152);
#if HAS_TCGEN05
    const uint64_t dAh = make_desc(tb);
    const uint64_t dAl = make_desc(tb + 16384);
    const uint64_t dBh = make_desc(tb + 32768);
    const uint64_t dBl = make_desc(tb + 49152);
#endif

    const int lda = (z == 0) ? D_N : (R_N * U_N);
    const float* Abase = (z == 0) ? inputs : (states + (z - 1) * U_N);
    const unsigned g8 = (unsigned)(tid & 7);     // 16B-group within 64-float row
    const unsigned arw = (unsigned)(tid >> 3);   // row base, 32 rows per pass

    for (int kc = 0; kc < KC_N; kc++) {
#if HAS_TCGEN05
        if (kc > 0) MBAR_WAIT(sb + 8, (unsigned)((kc - 1) & 1));
#endif
        // ---- A: load fp32, split to bf16 hi/lo, store SW128-swizzled ----
        {
            const float* srcb = Abase + (size_t)(mt * 128) * lda + kc * 64 + g8 * 8;
#pragma unroll
            for (int j = 0; j < 4; j++) {
                unsigned row = arw + j * 32;
                const float* src = srcb + (size_t)row * lda;
                float4 f0 = *(const float4*)src;
                float4 f1 = *(const float4*)(src + 4);
                float x[8] = {f0.x, f0.y, f0.z, f0.w, f1.x, f1.y, f1.z, f1.w};
                unsigned hs[8], lsv[8];
#pragma unroll
                for (int e = 0; e < 8; e++) {
                    __nv_bfloat16 h = __float2bfloat16_rn(x[e]);
                    hs[e] = (unsigned)__bfloat16_as_ushort(h);
                    lsv[e] = (unsigned)__bfloat16_as_ushort(
                        __float2bfloat16_rn(x[e] - __bfloat162float(h)));
                }
                uint4 uh, ul;
                uh.x = hs[0] | (hs[1] << 16); uh.y = hs[2] | (hs[3] << 16);
                uh.z = hs[4] | (hs[5] << 16); uh.w = hs[6] | (hs[7] << 16);
                ul.x = lsv[0] | (lsv[1] << 16); ul.y = lsv[2] | (lsv[3] << 16);
                ul.z = lsv[4] | (lsv[5] << 16); ul.w = lsv[6] | (lsv[7] << 16);
                unsigned byte = row * 128u + g8 * 16u;
                unsigned sw = byte ^ ((byte >> 3) & 0x70u);
                sAh[sw >> 4] = uh;
                sAl[sw >> 4] = ul;
            }
        }
        // ---- W: copy pre-swizzled bf16 tiles (identity uint4 copies) ----
        {
            const size_t tB = ((size_t)((z * NT_N + nt) * KC_N + kc)) * 1024;
#pragma unroll
            for (int j = 0; j < 4; j++) {
                int idx = tid + j * 256;
                sWh[idx] = gW_hi[tB + idx];
                sWl[idx] = gW_lo[tB + idx];
            }
        }
        asm volatile("fence.proxy.async.shared::cta;" ::: "memory");
        __syncthreads();
#if HAS_TCGEN05
        if (wid == 0 && elect1()) {
#pragma unroll
            for (int ks = 0; ks < 4; ks++) {
                uint64_t off = (uint64_t)(ks * 2);
                mma_f16_ss(tmem, dAh + off, dBh + off, (kc == 0 && ks == 0) ? 0u : 1u);
                mma_f16_ss(tmem, dAh + off, dBl + off, 1u);
                mma_f16_ss(tmem, dAl + off, dBh + off, 1u);
            }
            asm volatile(
                "tcgen05.commit.cta_group::1.mbarrier::arrive::one.shared::cluster.b64 [%0];"
                :: "r"(sb + 8) : "memory");
        }
#else
        {
            const int frow = tid >> 1;
            const int fc0 = (tid & 1) * 64;
            for (int kk = 0; kk < 64; kk++) {
                float a = rd_bf16_sw((const char*)sAh, frow, kk)
                        + rd_bf16_sw((const char*)sAl, frow, kk);
#pragma unroll 8
                for (int j = 0; j < 64; j++) {
                    float bb = rd_bf16_sw((const char*)sWh, fc0 + j, kk)
                             + rd_bf16_sw((const char*)sWl, fc0 + j, kk);
                    facc[j] = fmaf(a, bb, facc[j]);
                }
            }
            __syncthreads();
        }
#endif
    }

#if HAS_TCGEN05
    MBAR_WAIT(sb + 8, 1u);   // 4th commit -> phase 3 -> parity 1
    asm volatile("tcgen05.fence::after_thread_sync;" ::: "memory");

    // Epilogue: TMEM -> swizzled SMEM staging -> coalesced global with bias.
    const int cb = (wid >> 2) * 64;
    const int row = (wid & 3) * 32 + lane;
#pragma unroll
    for (int half = 0; half < 2; half++) {
        uint32_t r[32];
        TC_LD_X32(r, tmem + (uint32_t)(cb + half * 32));
        asm volatile("tcgen05.wait::ld.sync.aligned;" ::: "memory");
#pragma unroll
        for (int q = 0; q < 8; q++) {
            int col = cb + half * 32 + q * 4;
            unsigned byte = (unsigned)row * 512u + (unsigned)col * 4u;
            unsigned phys = byte ^ (((unsigned)row & 7u) << 4);
            *(uint4*)(tbp + phys) = make_uint4(r[q*4+0], r[q*4+1], r[q*4+2], r[q*4+3]);
        }
    }
    __syncthreads();
    const int n0 = nt * 128;
#pragma unroll
    for (int it = 0; it < 16; it++) {
        int i2 = tid + it * 256;
        int rw = i2 >> 5, c4 = i2 & 31;
        unsigned byte = (unsigned)rw * 512u + (unsigned)c4 * 16u;
        unsigned phys = byte ^ (((unsigned)rw & 7u) << 4);
        uint4 v = *(const uint4*)(tbp + phys);
        float4 f;
        f.x = __uint_as_float(v.x); f.y = __uint_as_float(v.y);
        f.z = __uint_as_float(v.z); f.w = __uint_as_float(v.w);
        const float4 b4 = *(const float4*)(bias + (size_t)z * NX + n0 + c4 * 4);
        f.x += b4.x; f.y += b4.y; f.z += b4.z; f.w += b4.w;
        size_t rg = (size_t)mt * 128 + rw;
        float* dst = (z == 0)
            ? (g_mx + rg * NX + n0 + c4 * 4)
            : (g_inner + rg * (R_N * NX) + (size_t)(z - 1) * NX + n0 + c4 * 4);
        *(float4*)dst = f;
    }
    __syncthreads();
    if (tid == 0) MBAR_INVAL(sb + 8);
    __syncthreads();
    if (wid == 0) {
        asm volatile("tcgen05.dealloc.cta_group::1.sync.aligned.b32 %0, %1;"
                     :: "r"(tmem), "r"(128u));
    }
#else
    {
        const int frow = tid >> 1;
        const int fc0 = (tid & 1) * 64;
        const int n0 = nt * 128;
        size_t rg = (size_t)mt * 128 + frow;
#pragma unroll 8
        for (int j = 0; j < 64; j++) {
            float f = facc[j] + bias[(size_t)z * NX + n0 + fc0 + j];
            float* dst = (z == 0)
                ? (g_mx + rg * NX + n0 + fc0 + j)
                : (g_inner + rg * (R_N * NX) + (size_t)(z - 1) * NX + n0 + fc0 + j);
            *dst = f;
        }
    }
#endif
}

// ---------------- vectorized fused epilogue: 4 rows/block, float4/thread ----------------
static __device__ __forceinline__ float4 ld4(const float* p) { return *(const float4*)p; }

__global__ void __launch_bounds__(256) fuse_kernel(
    const float* __restrict__ states,
    const int* __restrict__ cell_mask,
    const float* __restrict__ v,
    float* __restrict__ out)
{
    const int rin = threadIdx.x >> 6;                 // row in block 0..3
    const int b = blockIdx.x * 4 + rin;
    const int t = threadIdx.x & 63;
    const int u0 = t * 4;

    const float* mxp = g_mx + (size_t)b * NX;
    const float4 xz = ld4(mxp + u0);
    const float4 xr = ld4(mxp + U_N + u0);
    const float4 xh = ld4(mxp + 2 * U_N + u0);

    bool m[R_N];
#pragma unroll
    for (int r = 0; r < R_N; r++) m[r] = cell_mask[b * R_N + r] != 0;

    float4 rz[R_N];
    float4 acc = make_float4(0.f, 0.f, 0.f, 0.f);
#pragma unroll
    for (int r = 0; r < R_N; r++) {
        const float* ip = g_inner + (size_t)b * (R_N * NX) + (size_t)r * NX;
        rz[r] = ld4(ip + u0);
        const float4 rr  = ld4(ip + U_N + u0);
        const float4 rhc = ld4(ip + 2 * U_N + u0);
        if (m[r]) {
            acc.x += rhc.x / (1.0f + expf(-(xr.x + rr.x)));
            acc.y += rhc.y / (1.0f + expf(-(xr.y + rr.y)));
            acc.z += rhc.z / (1.0f + expf(-(xr.z + rr.z)));
            acc.w += rhc.w / (1.0f + expf(-(xr.w + rr.w)));
        }
    }
    float4 hh;
    hh.x = tanhf(xh.x + acc.x * 0.25f);
    hh.y = tanhf(xh.y + acc.y * 0.25f);
    hh.z = tanhf(xh.z + acc.z * 0.25f);
    hh.w = tanhf(xh.w + acc.w * 0.25f);

    const float4 vv = ld4(v + u0);
    float part[R_N + 1];
#pragma unroll
    for (int r = 0; r < R_N; r++) {
        part[r] = tanhf(xz.x + rz[r].x) * vv.x + tanhf(xz.y + rz[r].y) * vv.y
                + tanhf(xz.z + rz[r].z) * vv.z + tanhf(xz.w + rz[r].w) * vv.w;
    }
    part[R_N] = tanhf(xz.x + hh.x) * vv.x + tanhf(xz.y + hh.y) * vv.y
              + tanhf(xz.z + hh.z) * vv.z + tanhf(xz.w + hh.w) * vv.w;

    __shared__ float wsum[8][R_N + 1];
    const int warp = threadIdx.x >> 5;
    const int lane = threadIdx.x & 31;
#pragma unroll
    for (int k = 0; k < R_N + 1; k++) {
        float s = part[k];
#pragma unroll
        for (int off = 16; off > 0; off >>= 1)
            s += __shfl_down_sync(0xffffffffu, s, off);
        if (lane == 0) wsum[warp][k] = s;
    }
    __shared__ float prob_s[4][R_N + 1];
    __syncthreads();
    if (t == 0) {
        float logit[R_N + 1];
        float mx = -INFINITY;
#pragma unroll
        for (int k = 0; k < R_N + 1; k++) {
            float s = wsum[rin * 2][k] + wsum[rin * 2 + 1][k];
            const bool ok = (k == R_N) ? true : m[k];
            logit[k] = ok ? s : -INFINITY;
            mx = fmaxf(mx, logit[k]);
        }
        float denom = 0.f;
        float e[R_N + 1];
#pragma unroll
        for (int k = 0; k < R_N + 1; k++) {
            e[k] = (logit[k] == -INFINITY) ? 0.f : expf(logit[k] - mx);
            denom += e[k];
        }
#pragma unroll
        for (int k = 0; k < R_N + 1; k++) prob_s[rin][k] = e[k] / denom;
    }
    __syncthreads();

    float4 h = make_float4(0.f, 0.f, 0.f, 0.f);
#pragma unroll
    for (int r = 0; r < R_N; r++) {
        const float4 st = ld4(states + (size_t)b * (R_N * U_N) + r * U_N + u0);
        const float p = prob_s[rin][r];
        h.x += st.x * p; h.y += st.y * p; h.z += st.z * p; h.w += st.w * p;
    }
    const float p4 = prob_s[rin][R_N];
    h.x += hh.x * p4; h.y += hh.y * p4; h.z += hh.z * p4; h.w += hh.w * p4;
    *(float4*)(out + (size_t)b * U_N + u0) = h;
}

extern "C" void kernel_launch(void* const* d_in, const int* in_sizes, int n_in,
                              void* d_out, int out_size) {
    const float* inputs    = (const float*)d_in[0];
    const float* states    = (const float*)d_in[1];
    /* d_in[2] = edge_types (dead in reference) */
    const int*   cell_mask = (const int*)d_in[3];
    const float* kernelW   = (const float*)d_in[4];
    const float* rkernel   = (const float*)d_in[5];
    const float* bias      = (const float*)d_in[6];
    const float* v         = (const float*)d_in[7];
    /* d_in[8] = edge_emb (dead in reference) */
    float* out = (float*)d_out;
    (void)in_sizes; (void)n_in; (void)out_size;

    cudaFuncSetAttribute(gemm_tc, cudaFuncAttributeMaxDynamicSharedMemorySize, DSMEM_BYTES);

    prep_W<<<480, 256>>>(kernelW, rkernel);
    gemm_tc<<<dim3(NT_N, MT_N, NZ), 256, DSMEM_BYTES>>>(inputs, states, bias);
    fuse_kernel<<<B_ROWS / 4, 256>>>(states, cell_mask, v, out);
}